// round 16
// baseline (speedup 1.0000x reference)
#include <cuda_runtime.h>
#include <cuda_bf16.h>
#include <cstdint>
#include <math.h>

// ---------------- problem constants ----------------
#define NT      16384
#define HID     4096
#define NE      64
#define NK      32768

#define OFF_W      0
#define OFF_IDX    32768
#define OFF_OFFS   65536
#define OFF_GATHER 65600
#define OFF_AUX    98368
#define OFF_Z      98369

// GEMM tiling
#define MTILE   64
#define KSPLIT  8
#define KPER    (HID / KSPLIT)      // 512
#define KC      64                  // bf16 K per chunk
#define NCHUNK  (KPER / KC)         // 8
#define NMT     (NT / MTILE)        // 256
#define NBLK    (NMT * KSPLIT)      // 2048 CTAs
#define NCTA    128                 // metadata block count

// smem: padded rows, 64 bf16 + 8 pad = 144 bytes
#define RSTRIDE 144
#define A_BYTES (MTILE * RSTRIDE)   // 9216
#define B_BYTES (NE * RSTRIDE)      // 9216
#define SM_AHI  0
#define SM_ALO  (A_BYTES)
#define SM_BHI  (2 * A_BYTES)
#define SM_BLO  (2 * A_BYTES + B_BYTES)
#define BUF_BYTES (2 * A_BYTES + 2 * B_BYTES)  // 36864
#define SM_TOTAL  (2 * BUF_BYTES)              // 73728
#define LDL     68                  // logits stride (floats), 16B-aligned rows

// ---------------- device scratch ----------------
__device__ int g_flat[NK];
__device__ int g_bc[NE * NCTA];
__device__ __align__(16) __nv_bfloat16 g_whi[NE * HID];
__device__ __align__(16) __nv_bfloat16 g_wlo[NE * HID];
__device__ __align__(16) float g_part[KSPLIT * NT * NE];   // 32 MB partials

__device__ __forceinline__ unsigned pack_bf2(__nv_bfloat16 a, __nv_bfloat16 b) {
    return (unsigned)__bfloat16_as_ushort(a) | ((unsigned)__bfloat16_as_ushort(b) << 16);
}
__device__ __forceinline__ uint32_t smem_u32(const void* p) {
    uint32_t a;
    asm("{ .reg .u64 t; cvta.to.shared.u64 t, %1; cvt.u32.u64 %0, t; }" : "=r"(a) : "l"(p));
    return a;
}
__device__ __forceinline__ void mma16816(float* d, const uint32_t* a, const uint32_t* b) {
    asm volatile(
        "mma.sync.aligned.m16n8k16.row.col.f32.bf16.bf16.f32 "
        "{%0,%1,%2,%3}, {%4,%5,%6,%7}, {%8,%9}, {%0,%1,%2,%3};"
        : "+f"(d[0]), "+f"(d[1]), "+f"(d[2]), "+f"(d[3])
        : "r"(a[0]), "r"(a[1]), "r"(a[2]), "r"(a[3]), "r"(b[0]), "r"(b[1]));
}
#define LDSM4(r0, r1, r2, r3, a) \
    asm volatile("ldmatrix.sync.aligned.m8n8.x4.shared.b16 {%0,%1,%2,%3}, [%4];" \
                 : "=r"(r0), "=r"(r1), "=r"(r2), "=r"(r3) : "r"(a))
#define CP16(dst, src) \
    asm volatile("cp.async.ca.shared.global [%0], [%1], 16;" :: "r"(dst), "l"(src))
#define CP_COMMIT() asm volatile("cp.async.commit_group;" ::: "memory")
#define CP_WAIT0()  asm volatile("cp.async.wait_group 0;" ::: "memory")

// ===================================================================
// Kernel 0: preconvert gate_w to bf16 hi/lo (vectorized float4)
// ===================================================================
__global__ __launch_bounds__(256) void wconv_kernel(const float* __restrict__ w) {
    int i = blockIdx.x * 256 + threadIdx.x;       // float4 index
    float4 v = ((const float4*)w)[i];
    __nv_bfloat16 hx = __float2bfloat16_rn(v.x);
    __nv_bfloat16 hy = __float2bfloat16_rn(v.y);
    __nv_bfloat16 hz = __float2bfloat16_rn(v.z);
    __nv_bfloat16 hw = __float2bfloat16_rn(v.w);
    uint2 H, L;
    H.x = pack_bf2(hx, hy); H.y = pack_bf2(hz, hw);
    L.x = pack_bf2(__float2bfloat16_rn(v.x - __bfloat162float(hx)),
                   __float2bfloat16_rn(v.y - __bfloat162float(hy)));
    L.y = pack_bf2(__float2bfloat16_rn(v.z - __bfloat162float(hz)),
                   __float2bfloat16_rn(v.w - __bfloat162float(hw)));
    ((uint2*)g_whi)[i] = H;
    ((uint2*)g_wlo)[i] = L;
}

// ===================================================================
// Kernel 1: HMMA router GEMM (bf16 split), split-K partials
// grid = 2048 CTAs x 128 threads (4 warps: 2 M x 2 N, 32x32 each)
// [round-9/13 core: convert/store BEFORE compute — proven ordering]
// ===================================================================
__global__ __launch_bounds__(128, 3) void router_kernel(const float* __restrict__ x)
{
    extern __shared__ __align__(16) char smem[];
    const uint32_t sb = smem_u32(smem);
    const int tid  = threadIdx.x;
    const int wid  = tid >> 5;
    const int lane = tid & 31;
    const int mt   = blockIdx.x >> 3;          // M-tile
    const int ksp  = blockIdx.x & 7;           // K split
    const int row0 = mt * MTILE;

    const int wrow = wid >> 1;
    const int wcol = wid & 1;
    const int g = lane >> 2;
    const int q = lane & 3;

    const float4* x4 = (const float4*)x;
    int a_r[8], a_c4[8];
#pragma unroll
    for (int i = 0; i < 8; i++) {
        int u = tid + 128 * i;
        a_r[i]  = u >> 4;
        a_c4[i] = u & 15;
    }
    const int kaBase = ksp * (KPER / 4);

    int b_dst[4];
    long b_src[4];
#pragma unroll
    for (int j = 0; j < 4; j++) {
        int u = tid + 128 * j;
        int r = u >> 3, c = u & 7;
        b_dst[j] = r * RSTRIDE + c * 16;
        b_src[j] = (long)r * (HID * 2) + c * 16;
    }
    const long kbByte = (long)ksp * KPER * 2;
    const char* whiB = (const char*)g_whi + kbByte;
    const char* wloB = (const char*)g_wlo + kbByte;

    const uint32_t addrA = sb + SM_AHI + (wrow * 32 + (lane & 15)) * RSTRIDE
                         + ((lane >> 4) * 16);
    const uint32_t addrB = sb + SM_BHI + (wcol * 32 + ((lane >> 4) & 1) * 8 + (lane & 7)) * RSTRIDE
                         + (((lane >> 3) & 1) * 16);

    float acc[2][4][4];
#pragma unroll
    for (int mi = 0; mi < 2; mi++)
#pragma unroll
        for (int ni = 0; ni < 4; ni++)
#pragma unroll
            for (int c = 0; c < 4; c++) acc[mi][ni][c] = 0.f;

    float4 pa[8];

    // ---- preload: chunk 0 into buf0 ----
    {
#pragma unroll
        for (int j = 0; j < 4; j++) {
            CP16(sb + SM_BHI + b_dst[j], whiB + b_src[j]);
            CP16(sb + SM_BLO + b_dst[j], wloB + b_src[j]);
        }
        CP_COMMIT();
#pragma unroll
        for (int i = 0; i < 8; i++)
            pa[i] = x4[(size_t)(row0 + a_r[i]) * (HID / 4) + kaBase + a_c4[i]];
#pragma unroll
        for (int i = 0; i < 8; i++) {
            float4 v = pa[i];
            __nv_bfloat16 hx = __float2bfloat16_rn(v.x);
            __nv_bfloat16 hy = __float2bfloat16_rn(v.y);
            __nv_bfloat16 hz = __float2bfloat16_rn(v.z);
            __nv_bfloat16 hw = __float2bfloat16_rn(v.w);
            uint2 H, L;
            H.x = pack_bf2(hx, hy); H.y = pack_bf2(hz, hw);
            L.x = pack_bf2(__float2bfloat16_rn(v.x - __bfloat162float(hx)),
                           __float2bfloat16_rn(v.y - __bfloat162float(hy)));
            L.y = pack_bf2(__float2bfloat16_rn(v.z - __bfloat162float(hz)),
                           __float2bfloat16_rn(v.w - __bfloat162float(hw)));
            int off = a_r[i] * RSTRIDE + a_c4[i] * 8;
            *(uint2*)(smem + SM_AHI + off) = H;
            *(uint2*)(smem + SM_ALO + off) = L;
        }
#pragma unroll
        for (int i = 0; i < 8; i++)
            pa[i] = x4[(size_t)(row0 + a_r[i]) * (HID / 4) + kaBase + (KC / 4) + a_c4[i]];
        CP_WAIT0();
        __syncthreads();
    }

#pragma unroll 1
    for (int s = 0; s < NCHUNK; ++s) {
        const int cur = (s & 1) * BUF_BYTES;
        const int nxt = ((s + 1) & 1) * BUF_BYTES;

        if (s + 1 < NCHUNK) {
            // store A chunk s+1 (held in pa) to nxt buffer
#pragma unroll
            for (int i = 0; i < 8; i++) {
                float4 v = pa[i];
                __nv_bfloat16 hx = __float2bfloat16_rn(v.x);
                __nv_bfloat16 hy = __float2bfloat16_rn(v.y);
                __nv_bfloat16 hz = __float2bfloat16_rn(v.z);
                __nv_bfloat16 hw = __float2bfloat16_rn(v.w);
                uint2 H, L;
                H.x = pack_bf2(hx, hy); H.y = pack_bf2(hz, hw);
                L.x = pack_bf2(__float2bfloat16_rn(v.x - __bfloat162float(hx)),
                               __float2bfloat16_rn(v.y - __bfloat162float(hy)));
                L.y = pack_bf2(__float2bfloat16_rn(v.z - __bfloat162float(hz)),
                               __float2bfloat16_rn(v.w - __bfloat162float(hw)));
                int off = a_r[i] * RSTRIDE + a_c4[i] * 8;
                *(uint2*)(smem + nxt + SM_AHI + off) = H;
                *(uint2*)(smem + nxt + SM_ALO + off) = L;
            }
            // B chunk s+1 via cp.async
            const long kb = (long)(s + 1) * KC * 2;
#pragma unroll
            for (int j = 0; j < 4; j++) {
                CP16(sb + nxt + SM_BHI + b_dst[j], whiB + kb + b_src[j]);
                CP16(sb + nxt + SM_BLO + b_dst[j], wloB + kb + b_src[j]);
            }
            CP_COMMIT();
            // prefetch A chunk s+2
            if (s + 2 < NCHUNK) {
                const int ka = kaBase + (s + 2) * (KC / 4);
#pragma unroll
                for (int i = 0; i < 8; i++)
                    pa[i] = x4[(size_t)(row0 + a_r[i]) * (HID / 4) + ka + a_c4[i]];
            }
        }

        // ---- compute chunk s from cur buffer ----
        const uint32_t aA = addrA + cur;
        const uint32_t aB = addrB + cur;
#pragma unroll
        for (int ks = 0; ks < 4; ++ks) {
            uint32_t Ah0[4], Ah1[4], Al0[4], Al1[4];
            LDSM4(Ah0[0], Ah0[1], Ah0[2], Ah0[3], aA + ks * 32);
            LDSM4(Ah1[0], Ah1[1], Ah1[2], Ah1[3], aA + 16 * RSTRIDE + ks * 32);
            LDSM4(Al0[0], Al0[1], Al0[2], Al0[3], aA + A_BYTES + ks * 32);
            LDSM4(Al1[0], Al1[1], Al1[2], Al1[3], aA + A_BYTES + 16 * RSTRIDE + ks * 32);
            uint32_t Bh[4][2], Bl[4][2];
            LDSM4(Bh[0][0], Bh[0][1], Bh[1][0], Bh[1][1], aB + ks * 32);
            LDSM4(Bh[2][0], Bh[2][1], Bh[3][0], Bh[3][1], aB + 16 * RSTRIDE + ks * 32);
            LDSM4(Bl[0][0], Bl[0][1], Bl[1][0], Bl[1][1], aB + B_BYTES + ks * 32);
            LDSM4(Bl[2][0], Bl[2][1], Bl[3][0], Bl[3][1], aB + B_BYTES + 16 * RSTRIDE + ks * 32);
#pragma unroll
            for (int ni = 0; ni < 4; ni++) {
                mma16816(acc[0][ni], Ah0, Bh[ni]);
                mma16816(acc[0][ni], Ah0, Bl[ni]);
                mma16816(acc[0][ni], Al0, Bh[ni]);
                mma16816(acc[1][ni], Ah1, Bh[ni]);
                mma16816(acc[1][ni], Ah1, Bl[ni]);
                mma16816(acc[1][ni], Al1, Bh[ni]);
            }
        }

        if (s + 1 < NCHUNK) {
            CP_WAIT0();
            __syncthreads();
        }
    }

    // ---- stage logits (buf0; last chunk computed from buf1) ----
    float* lsm = (float*)smem;
#pragma unroll
    for (int mi = 0; mi < 2; mi++)
#pragma unroll
        for (int ni = 0; ni < 4; ni++) {
            int r = wrow * 32 + mi * 16 + g;
            int c = wcol * 32 + ni * 8 + q * 2;
            lsm[r * LDL + c]           = acc[mi][ni][0];
            lsm[r * LDL + c + 1]       = acc[mi][ni][1];
            lsm[(r + 8) * LDL + c]     = acc[mi][ni][2];
            lsm[(r + 8) * LDL + c + 1] = acc[mi][ni][3];
        }
    __syncthreads();

    // coalesced store: 64 tokens x 64 floats, 2 threads/token
    {
        int tok = tid >> 1;
        int qo  = (tid & 1) * 32;
        float* gp = g_part + (size_t)ksp * NT * NE + (size_t)(row0 + tok) * NE + qo;
        const float* ls = &lsm[tok * LDL + qo];
#pragma unroll
        for (int v = 0; v < 8; v++)
            ((float4*)gp)[v] = *(const float4*)(ls + 4 * v);
    }
}

// ===================================================================
// Kernel 2: reduce partials + softmax + top2 + hist
// grid = 128 blocks x 128 threads (one token per thread)
// ===================================================================
__global__ __launch_bounds__(128) void epi_kernel(float* __restrict__ out)
{
    __shared__ int hist[NE];
    const int t = threadIdx.x;
    const int blk = blockIdx.x;
    const int n = blk * 128 + t;

    if (t < NE) hist[t] = 0;
    __syncthreads();

    float l[NE];
    {
        const float4* p0 = (const float4*)(g_part + (size_t)n * NE);
#pragma unroll
        for (int v = 0; v < 16; v++) {
            float4 a = p0[v];
            l[4*v] = a.x; l[4*v+1] = a.y; l[4*v+2] = a.z; l[4*v+3] = a.w;
        }
#pragma unroll
        for (int ks = 1; ks < KSPLIT; ks++) {
            const float4* p = (const float4*)(g_part + (size_t)ks * NT * NE + (size_t)n * NE);
#pragma unroll
            for (int v = 0; v < 16; v++) {
                float4 a = p[v];
                l[4*v] += a.x; l[4*v+1] += a.y; l[4*v+2] += a.z; l[4*v+3] += a.w;
            }
        }
    }

    float mx = -3.0e38f;
#pragma unroll
    for (int e = 0; e < NE; ++e) mx = fmaxf(mx, l[e]);
    float Z = 0.f;
#pragma unroll
    for (int e = 0; e < NE; ++e) Z += expf(l[e] - mx);

    float m1 = -3.0e38f, m2 = -3.0e38f;
    int i1 = 0, i2 = 0;
#pragma unroll
    for (int e = 0; e < NE; ++e) {
        float v = l[e];
        if (v > m1) { m2 = m1; i2 = i1; m1 = v; i1 = e; }
        else if (v > m2) { m2 = v; i2 = e; }
    }
    float p1 = expf(m1 - mx) / Z;
    float p2 = expf(m2 - mx) / Z;
    float sN = p1 + p2 + 1e-8f;

    out[OFF_W + 2 * n]       = p1 / sN;
    out[OFF_W + 2 * n + 1]   = p2 / sN;
    out[OFF_IDX + 2 * n]     = (float)i1;
    out[OFF_IDX + 2 * n + 1] = (float)i2;
    g_flat[2 * n]     = i1;
    g_flat[2 * n + 1] = i2;
    atomicAdd(&hist[i1], 1);
    atomicAdd(&hist[i2], 1);
    __syncthreads();
    if (t < NE) g_bc[t * NCTA + blk] = hist[t];
}

// ===================================================================
// Kernel 3: fused scan + stable placement -> gather + offsets
// 128 blocks x 256 threads; g_bc staged through smem (32KB)
// ===================================================================
__global__ __launch_bounds__(256) void place_kernel(float* __restrict__ out) {
    __shared__ int sbc[NE * NCTA];     // 8192 ints = 32KB
    __shared__ int wsum[8];
    __shared__ int soff[NE];
    __shared__ int cnt[8][NE];
    const int t = threadIdx.x, blk = blockIdx.x;
    const int lane = t & 31, w = t >> 5;

    // coalesced staged load of g_bc
#pragma unroll
    for (int j = 0; j < 8; j++)
        ((int4*)sbc)[t + 256 * j] = ((const int4*)g_bc)[t + 256 * j];
    for (int i = t; i < 8 * NE; i += 256) ((int*)cnt)[i] = 0;
    __syncthreads();

    // thread t scans sbc[t*32 .. t*32+31] (expert t>>2, quarter t&3)
    int vsum = 0, pre_at = 0;
    const int want = blk >> 5;       // thread quarter holding index blk
    const int li   = blk & 31;
#pragma unroll
    for (int i = 0; i < 32; i++) {
        int c = sbc[t * 32 + i];
        if (i == li) pre_at = vsum;
        vsum += c;
    }
    int inc = vsum;
#pragma unroll
    for (int d = 1; d < 32; d <<= 1) {
        int o = __shfl_up_sync(0xffffffffu, inc, d);
        if (lane >= d) inc += o;
    }
    if (lane == 31) wsum[w] = inc;
    __syncthreads();
    if (w == 0) {
        int z = (lane < 8) ? wsum[lane] : 0;
#pragma unroll
        for (int d = 1; d < 8; d <<= 1) {
            int o = __shfl_up_sync(0xffffffffu, z, d);
            if (lane >= d) z += o;
        }
        if (lane < 8) wsum[lane] = z;
    }
    __syncthreads();
    int tbase = (w > 0 ? wsum[w - 1] : 0) + (inc - vsum);  // exclusive base

    if ((t & 3) == want) soff[t >> 2] = tbase + pre_at;
    if (blk == 0 && (t & 3) == 3) out[OFF_OFFS + (t >> 2)] = (float)(tbase + vsum);
    if (blk == 0 && t == 0) { out[OFF_AUX] = 0.f; out[OFF_Z] = 0.f; }
    __syncthreads();

    // stable placement within this block's 256 slots
    const int i = blk * 256 + t;
    const int e = g_flat[i];
    unsigned m = __match_any_sync(0xffffffffu, e);
    int r = __popc(m & ((1u << lane) - 1u));
    if (r == 0) cnt[w][e] = __popc(m);
    __syncthreads();

    int woff = 0;
#pragma unroll
    for (int ww = 0; ww < 8; ww++)
        if (ww < w) woff += cnt[ww][e];

    out[OFF_GATHER + soff[e] + woff + r] = (float)i;
}

// ===================================================================
extern "C" void kernel_launch(void* const* d_in, const int* in_sizes, int n_in,
                              void* d_out, int out_size)
{
    const float* x = (const float*)d_in[0];
    const float* w = (const float*)d_in[1];
    float* out = (float*)d_out;

    cudaFuncSetAttribute(router_kernel, cudaFuncAttributeMaxDynamicSharedMemorySize, SM_TOTAL);

    wconv_kernel<<<(NE * HID) / 1024, 256>>>(w);
    router_kernel<<<NBLK, 128, SM_TOTAL>>>(x);
    epi_kernel<<<NCTA, 128>>>(out);
    place_kernel<<<NCTA, 256>>>(out);
}

// round 17
// speedup vs baseline: 1.3640x; 1.3640x over previous
#include <cuda_runtime.h>
#include <cuda_bf16.h>
#include <cstdint>
#include <math.h>

// ---------------- problem constants ----------------
#define NT      16384
#define HID     4096
#define NE      64
#define NK      32768

#define OFF_W      0
#define OFF_IDX    32768
#define OFF_OFFS   65536
#define OFF_GATHER 65600
#define OFF_AUX    98368
#define OFF_Z      98369

// GEMM tiling
#define MTILE   64
#define KSPLIT  8
#define KPER    (HID / KSPLIT)      // 512
#define KC      64                  // bf16 K per chunk
#define NCHUNK  (KPER / KC)         // 8
#define NMT     (NT / MTILE)        // 256
#define NBLK    (NMT * KSPLIT)      // 2048 CTAs
#define NCTA    128                 // metadata block count

// smem: padded rows, 64 bf16 + 8 pad = 144 bytes
#define RSTRIDE 144
#define A_BYTES (MTILE * RSTRIDE)   // 9216
#define B_BYTES (NE * RSTRIDE)      // 9216
#define SM_AHI  0
#define SM_ALO  (A_BYTES)
#define SM_BHI  (2 * A_BYTES)
#define SM_BLO  (2 * A_BYTES + B_BYTES)
#define BUF_BYTES (2 * A_BYTES + 2 * B_BYTES)  // 36864
#define SM_TOTAL  (2 * BUF_BYTES)              // 73728
#define LDL     68                  // logits stride (floats), 16B-aligned rows

// ---------------- device scratch ----------------
__device__ int g_flat[NK];
__device__ int g_bc[NE * NCTA];
__device__ __align__(16) __nv_bfloat16 g_whi[NE * HID];
__device__ __align__(16) __nv_bfloat16 g_wlo[NE * HID];
__device__ __align__(16) float g_part[KSPLIT * NT * NE];   // 32 MB partials

__device__ __forceinline__ unsigned pack_bf2(__nv_bfloat16 a, __nv_bfloat16 b) {
    return (unsigned)__bfloat16_as_ushort(a) | ((unsigned)__bfloat16_as_ushort(b) << 16);
}
__device__ __forceinline__ uint32_t smem_u32(const void* p) {
    uint32_t a;
    asm("{ .reg .u64 t; cvta.to.shared.u64 t, %1; cvt.u32.u64 %0, t; }" : "=r"(a) : "l"(p));
    return a;
}
__device__ __forceinline__ void mma16816(float* d, const uint32_t* a, const uint32_t* b) {
    asm volatile(
        "mma.sync.aligned.m16n8k16.row.col.f32.bf16.bf16.f32 "
        "{%0,%1,%2,%3}, {%4,%5,%6,%7}, {%8,%9}, {%0,%1,%2,%3};"
        : "+f"(d[0]), "+f"(d[1]), "+f"(d[2]), "+f"(d[3])
        : "r"(a[0]), "r"(a[1]), "r"(a[2]), "r"(a[3]), "r"(b[0]), "r"(b[1]));
}
#define LDSM4(r0, r1, r2, r3, a) \
    asm volatile("ldmatrix.sync.aligned.m8n8.x4.shared.b16 {%0,%1,%2,%3}, [%4];" \
                 : "=r"(r0), "=r"(r1), "=r"(r2), "=r"(r3) : "r"(a))
#define CP16(dst, src) \
    asm volatile("cp.async.ca.shared.global [%0], [%1], 16;" :: "r"(dst), "l"(src))
#define CP_COMMIT() asm volatile("cp.async.commit_group;" ::: "memory")
#define CP_WAIT0()  asm volatile("cp.async.wait_group 0;" ::: "memory")

// ===================================================================
// Kernel 0: preconvert gate_w to bf16 hi/lo (vectorized float4)
// ===================================================================
__global__ __launch_bounds__(256) void wconv_kernel(const float* __restrict__ w) {
    int i = blockIdx.x * 256 + threadIdx.x;       // float4 index
    float4 v = ((const float4*)w)[i];
    __nv_bfloat16 hx = __float2bfloat16_rn(v.x);
    __nv_bfloat16 hy = __float2bfloat16_rn(v.y);
    __nv_bfloat16 hz = __float2bfloat16_rn(v.z);
    __nv_bfloat16 hw = __float2bfloat16_rn(v.w);
    uint2 H, L;
    H.x = pack_bf2(hx, hy); H.y = pack_bf2(hz, hw);
    L.x = pack_bf2(__float2bfloat16_rn(v.x - __bfloat162float(hx)),
                   __float2bfloat16_rn(v.y - __bfloat162float(hy)));
    L.y = pack_bf2(__float2bfloat16_rn(v.z - __bfloat162float(hz)),
                   __float2bfloat16_rn(v.w - __bfloat162float(hw)));
    ((uint2*)g_whi)[i] = H;
    ((uint2*)g_wlo)[i] = L;
}

// ===================================================================
// Kernel 1: HMMA router GEMM (bf16 split), split-K partials
// grid = 2048 CTAs x 128 threads (4 warps: 2 M x 2 N, 32x32 each)
// [round-9/13 core: convert/store BEFORE compute — proven ordering]
// ===================================================================
__global__ __launch_bounds__(128, 3) void router_kernel(const float* __restrict__ x)
{
    extern __shared__ __align__(16) char smem[];
    const uint32_t sb = smem_u32(smem);
    const int tid  = threadIdx.x;
    const int wid  = tid >> 5;
    const int lane = tid & 31;
    const int mt   = blockIdx.x >> 3;          // M-tile
    const int ksp  = blockIdx.x & 7;           // K split
    const int row0 = mt * MTILE;

    const int wrow = wid >> 1;
    const int wcol = wid & 1;
    const int g = lane >> 2;
    const int q = lane & 3;

    const float4* x4 = (const float4*)x;
    int a_r[8], a_c4[8];
#pragma unroll
    for (int i = 0; i < 8; i++) {
        int u = tid + 128 * i;
        a_r[i]  = u >> 4;
        a_c4[i] = u & 15;
    }
    const int kaBase = ksp * (KPER / 4);

    int b_dst[4];
    long b_src[4];
#pragma unroll
    for (int j = 0; j < 4; j++) {
        int u = tid + 128 * j;
        int r = u >> 3, c = u & 7;
        b_dst[j] = r * RSTRIDE + c * 16;
        b_src[j] = (long)r * (HID * 2) + c * 16;
    }
    const long kbByte = (long)ksp * KPER * 2;
    const char* whiB = (const char*)g_whi + kbByte;
    const char* wloB = (const char*)g_wlo + kbByte;

    const uint32_t addrA = sb + SM_AHI + (wrow * 32 + (lane & 15)) * RSTRIDE
                         + ((lane >> 4) * 16);
    const uint32_t addrB = sb + SM_BHI + (wcol * 32 + ((lane >> 4) & 1) * 8 + (lane & 7)) * RSTRIDE
                         + (((lane >> 3) & 1) * 16);

    float acc[2][4][4];
#pragma unroll
    for (int mi = 0; mi < 2; mi++)
#pragma unroll
        for (int ni = 0; ni < 4; ni++)
#pragma unroll
            for (int c = 0; c < 4; c++) acc[mi][ni][c] = 0.f;

    float4 pa[8];

    // ---- preload: chunk 0 into buf0 ----
    {
#pragma unroll
        for (int j = 0; j < 4; j++) {
            CP16(sb + SM_BHI + b_dst[j], whiB + b_src[j]);
            CP16(sb + SM_BLO + b_dst[j], wloB + b_src[j]);
        }
        CP_COMMIT();
#pragma unroll
        for (int i = 0; i < 8; i++)
            pa[i] = x4[(size_t)(row0 + a_r[i]) * (HID / 4) + kaBase + a_c4[i]];
#pragma unroll
        for (int i = 0; i < 8; i++) {
            float4 v = pa[i];
            __nv_bfloat16 hx = __float2bfloat16_rn(v.x);
            __nv_bfloat16 hy = __float2bfloat16_rn(v.y);
            __nv_bfloat16 hz = __float2bfloat16_rn(v.z);
            __nv_bfloat16 hw = __float2bfloat16_rn(v.w);
            uint2 H, L;
            H.x = pack_bf2(hx, hy); H.y = pack_bf2(hz, hw);
            L.x = pack_bf2(__float2bfloat16_rn(v.x - __bfloat162float(hx)),
                           __float2bfloat16_rn(v.y - __bfloat162float(hy)));
            L.y = pack_bf2(__float2bfloat16_rn(v.z - __bfloat162float(hz)),
                           __float2bfloat16_rn(v.w - __bfloat162float(hw)));
            int off = a_r[i] * RSTRIDE + a_c4[i] * 8;
            *(uint2*)(smem + SM_AHI + off) = H;
            *(uint2*)(smem + SM_ALO + off) = L;
        }
#pragma unroll
        for (int i = 0; i < 8; i++)
            pa[i] = x4[(size_t)(row0 + a_r[i]) * (HID / 4) + kaBase + (KC / 4) + a_c4[i]];
        CP_WAIT0();
        __syncthreads();
    }

#pragma unroll 1
    for (int s = 0; s < NCHUNK; ++s) {
        const int cur = (s & 1) * BUF_BYTES;
        const int nxt = ((s + 1) & 1) * BUF_BYTES;

        if (s + 1 < NCHUNK) {
            // store A chunk s+1 (held in pa) to nxt buffer
#pragma unroll
            for (int i = 0; i < 8; i++) {
                float4 v = pa[i];
                __nv_bfloat16 hx = __float2bfloat16_rn(v.x);
                __nv_bfloat16 hy = __float2bfloat16_rn(v.y);
                __nv_bfloat16 hz = __float2bfloat16_rn(v.z);
                __nv_bfloat16 hw = __float2bfloat16_rn(v.w);
                uint2 H, L;
                H.x = pack_bf2(hx, hy); H.y = pack_bf2(hz, hw);
                L.x = pack_bf2(__float2bfloat16_rn(v.x - __bfloat162float(hx)),
                               __float2bfloat16_rn(v.y - __bfloat162float(hy)));
                L.y = pack_bf2(__float2bfloat16_rn(v.z - __bfloat162float(hz)),
                               __float2bfloat16_rn(v.w - __bfloat162float(hw)));
                int off = a_r[i] * RSTRIDE + a_c4[i] * 8;
                *(uint2*)(smem + nxt + SM_AHI + off) = H;
                *(uint2*)(smem + nxt + SM_ALO + off) = L;
            }
            // B chunk s+1 via cp.async
            const long kb = (long)(s + 1) * KC * 2;
#pragma unroll
            for (int j = 0; j < 4; j++) {
                CP16(sb + nxt + SM_BHI + b_dst[j], whiB + kb + b_src[j]);
                CP16(sb + nxt + SM_BLO + b_dst[j], wloB + kb + b_src[j]);
            }
            CP_COMMIT();
            // prefetch A chunk s+2
            if (s + 2 < NCHUNK) {
                const int ka = kaBase + (s + 2) * (KC / 4);
#pragma unroll
                for (int i = 0; i < 8; i++)
                    pa[i] = x4[(size_t)(row0 + a_r[i]) * (HID / 4) + ka + a_c4[i]];
            }
        }

        // ---- compute chunk s from cur buffer ----
        const uint32_t aA = addrA + cur;
        const uint32_t aB = addrB + cur;
#pragma unroll
        for (int ks = 0; ks < 4; ++ks) {
            uint32_t Ah0[4], Ah1[4], Al0[4], Al1[4];
            LDSM4(Ah0[0], Ah0[1], Ah0[2], Ah0[3], aA + ks * 32);
            LDSM4(Ah1[0], Ah1[1], Ah1[2], Ah1[3], aA + 16 * RSTRIDE + ks * 32);
            LDSM4(Al0[0], Al0[1], Al0[2], Al0[3], aA + A_BYTES + ks * 32);
            LDSM4(Al1[0], Al1[1], Al1[2], Al1[3], aA + A_BYTES + 16 * RSTRIDE + ks * 32);
            uint32_t Bh[4][2], Bl[4][2];
            LDSM4(Bh[0][0], Bh[0][1], Bh[1][0], Bh[1][1], aB + ks * 32);
            LDSM4(Bh[2][0], Bh[2][1], Bh[3][0], Bh[3][1], aB + 16 * RSTRIDE + ks * 32);
            LDSM4(Bl[0][0], Bl[0][1], Bl[1][0], Bl[1][1], aB + B_BYTES + ks * 32);
            LDSM4(Bl[2][0], Bl[2][1], Bl[3][0], Bl[3][1], aB + B_BYTES + 16 * RSTRIDE + ks * 32);
#pragma unroll
            for (int ni = 0; ni < 4; ni++) {
                mma16816(acc[0][ni], Ah0, Bh[ni]);
                mma16816(acc[0][ni], Ah0, Bl[ni]);
                mma16816(acc[0][ni], Al0, Bh[ni]);
                mma16816(acc[1][ni], Ah1, Bh[ni]);
                mma16816(acc[1][ni], Ah1, Bl[ni]);
                mma16816(acc[1][ni], Al1, Bh[ni]);
            }
        }

        if (s + 1 < NCHUNK) {
            CP_WAIT0();
            __syncthreads();
        }
    }

    // ---- stage logits (buf0; last chunk computed from buf1) ----
    float* lsm = (float*)smem;
#pragma unroll
    for (int mi = 0; mi < 2; mi++)
#pragma unroll
        for (int ni = 0; ni < 4; ni++) {
            int r = wrow * 32 + mi * 16 + g;
            int c = wcol * 32 + ni * 8 + q * 2;
            lsm[r * LDL + c]           = acc[mi][ni][0];
            lsm[r * LDL + c + 1]       = acc[mi][ni][1];
            lsm[(r + 8) * LDL + c]     = acc[mi][ni][2];
            lsm[(r + 8) * LDL + c + 1] = acc[mi][ni][3];
        }
    __syncthreads();

    // coalesced store: 64 tokens x 64 floats, 2 threads/token
    {
        int tok = tid >> 1;
        int qo  = (tid & 1) * 32;
        float* gp = g_part + (size_t)ksp * NT * NE + (size_t)(row0 + tok) * NE + qo;
        const float* ls = &lsm[tok * LDL + qo];
#pragma unroll
        for (int v = 0; v < 8; v++)
            ((float4*)gp)[v] = *(const float4*)(ls + 4 * v);
    }
}

// ===================================================================
// Kernel 2: reduce partials + softmax + top2 + hist
// grid = 128 blocks x 128 threads (one token per thread)
// ===================================================================
__global__ __launch_bounds__(128) void epi_kernel(float* __restrict__ out)
{
    __shared__ int hist[NE];
    const int t = threadIdx.x;
    const int blk = blockIdx.x;
    const int n = blk * 128 + t;

    if (t < NE) hist[t] = 0;
    __syncthreads();

    float l[NE];
    {
        const float4* p0 = (const float4*)(g_part + (size_t)n * NE);
#pragma unroll
        for (int v = 0; v < 16; v++) {
            float4 a = p0[v];
            l[4*v] = a.x; l[4*v+1] = a.y; l[4*v+2] = a.z; l[4*v+3] = a.w;
        }
#pragma unroll
        for (int ks = 1; ks < KSPLIT; ks++) {
            const float4* p = (const float4*)(g_part + (size_t)ks * NT * NE + (size_t)n * NE);
#pragma unroll
            for (int v = 0; v < 16; v++) {
                float4 a = p[v];
                l[4*v] += a.x; l[4*v+1] += a.y; l[4*v+2] += a.z; l[4*v+3] += a.w;
            }
        }
    }

    float mx = -3.0e38f;
#pragma unroll
    for (int e = 0; e < NE; ++e) mx = fmaxf(mx, l[e]);
    float Z = 0.f;
#pragma unroll
    for (int e = 0; e < NE; ++e) Z += expf(l[e] - mx);

    float m1 = -3.0e38f, m2 = -3.0e38f;
    int i1 = 0, i2 = 0;
#pragma unroll
    for (int e = 0; e < NE; ++e) {
        float v = l[e];
        if (v > m1) { m2 = m1; i2 = i1; m1 = v; i1 = e; }
        else if (v > m2) { m2 = v; i2 = e; }
    }
    float p1 = expf(m1 - mx) / Z;
    float p2 = expf(m2 - mx) / Z;
    float sN = p1 + p2 + 1e-8f;

    out[OFF_W + 2 * n]       = p1 / sN;
    out[OFF_W + 2 * n + 1]   = p2 / sN;
    out[OFF_IDX + 2 * n]     = (float)i1;
    out[OFF_IDX + 2 * n + 1] = (float)i2;
    g_flat[2 * n]     = i1;
    g_flat[2 * n + 1] = i2;
    atomicAdd(&hist[i1], 1);
    atomicAdd(&hist[i2], 1);
    __syncthreads();
    if (t < NE) g_bc[t * NCTA + blk] = hist[t];
}

// ===================================================================
// Kernel 3: fused scan + stable placement -> gather + offsets
// 128 blocks x 256 threads; g_bc staged through smem (32KB)
// ===================================================================
__global__ __launch_bounds__(256) void place_kernel(float* __restrict__ out) {
    __shared__ int sbc[NE * NCTA];     // 8192 ints = 32KB
    __shared__ int wsum[8];
    __shared__ int soff[NE];
    __shared__ int cnt[8][NE];
    const int t = threadIdx.x, blk = blockIdx.x;
    const int lane = t & 31, w = t >> 5;

    // coalesced staged load of g_bc
#pragma unroll
    for (int j = 0; j < 8; j++)
        ((int4*)sbc)[t + 256 * j] = ((const int4*)g_bc)[t + 256 * j];
    for (int i = t; i < 8 * NE; i += 256) ((int*)cnt)[i] = 0;
    __syncthreads();

    // thread t scans sbc[t*32 .. t*32+31] (expert t>>2, quarter t&3)
    int vsum = 0, pre_at = 0;
    const int want = blk >> 5;       // thread quarter holding index blk
    const int li   = blk & 31;
#pragma unroll
    for (int i = 0; i < 32; i++) {
        int c = sbc[t * 32 + i];
        if (i == li) pre_at = vsum;
        vsum += c;
    }
    int inc = vsum;
#pragma unroll
    for (int d = 1; d < 32; d <<= 1) {
        int o = __shfl_up_sync(0xffffffffu, inc, d);
        if (lane >= d) inc += o;
    }
    if (lane == 31) wsum[w] = inc;
    __syncthreads();
    if (w == 0) {
        int z = (lane < 8) ? wsum[lane] : 0;
#pragma unroll
        for (int d = 1; d < 8; d <<= 1) {
            int o = __shfl_up_sync(0xffffffffu, z, d);
            if (lane >= d) z += o;
        }
        if (lane < 8) wsum[lane] = z;
    }
    __syncthreads();
    int tbase = (w > 0 ? wsum[w - 1] : 0) + (inc - vsum);  // exclusive base

    if ((t & 3) == want) soff[t >> 2] = tbase + pre_at;
    if (blk == 0 && (t & 3) == 3) out[OFF_OFFS + (t >> 2)] = (float)(tbase + vsum);
    if (blk == 0 && t == 0) { out[OFF_AUX] = 0.f; out[OFF_Z] = 0.f; }
    __syncthreads();

    // stable placement within this block's 256 slots
    const int i = blk * 256 + t;
    const int e = g_flat[i];
    unsigned m = __match_any_sync(0xffffffffu, e);
    int r = __popc(m & ((1u << lane) - 1u));
    if (r == 0) cnt[w][e] = __popc(m);
    __syncthreads();

    int woff = 0;
#pragma unroll
    for (int ww = 0; ww < 8; ww++)
        if (ww < w) woff += cnt[ww][e];

    out[OFF_GATHER + soff[e] + woff + r] = (float)i;
}

// ===================================================================
extern "C" void kernel_launch(void* const* d_in, const int* in_sizes, int n_in,
                              void* d_out, int out_size)
{
    const float* x = (const float*)d_in[0];
    const float* w = (const float*)d_in[1];
    float* out = (float*)d_out;

    cudaFuncSetAttribute(router_kernel, cudaFuncAttributeMaxDynamicSharedMemorySize, SM_TOTAL);

    wconv_kernel<<<(NE * HID) / 1024, 256>>>(w);
    router_kernel<<<NBLK, 128, SM_TOTAL>>>(x);
    epi_kernel<<<NCTA, 128>>>(out);
    place_kernel<<<NCTA, 256>>>(out);
}